// round 2
// baseline (speedup 1.0000x reference)
#include <cuda_runtime.h>
#include <cstdint>

#define B_DIM 128
#define L_DIM 12
#define F_DIM 4096
#define A_DIM 768
#define PAIRS 78   // sum_{i=0..11}(i+1)

#define BM 128
#define BN 128
#define BK 32
#define THREADS 256

// Scratch for per-(i,l) partial GEMMs: 78 * 128 * 768 floats = 30.7 MB (static, allowed)
__device__ float g_scratch[(size_t)PAIRS * B_DIM * A_DIM];

struct WPtrs { const float* w[12]; };

__device__ __forceinline__ uint32_t cvt_tf32(float f) {
    uint32_t o;
    asm volatile("cvt.rna.tf32.f32 %0, %1;" : "=r"(o) : "f"(f));
    return o;
}

__device__ __forceinline__ void cp16(uint32_t s, const float* g) {
    asm volatile("cp.async.cg.shared.global [%0], [%1], 16;" :: "r"(s), "l"(g));
}

// One CTA computes a 128x128 tile of P[pair] = x[:,l,:] @ W_i[l]  (K = 4096)
// smem layout per stage (8192 floats): As[128][32] then Bs[32][128],
// both with 16B-chunk XOR swizzle (chunk' = chunk ^ (row & 7)) so that
// cp.async 16B stores, ldmatrix A-frag reads and B LDS reads all work.
__global__ __launch_bounds__(THREADS)
void gemm_pair_kernel(const float* __restrict__ x, WPtrs wp) {
    extern __shared__ float sm[];
    const int tid  = threadIdx.x;
    const int lane = tid & 31;
    const int warp = tid >> 5;
    const int wm = (warp >> 2) * 64;   // warp row offset (2 warp-rows)
    const int wn = (warp & 3) * 32;    // warp col offset (4 warp-cols)

    // decode pair -> (i, l)
    int p = blockIdx.y;
    int i = 0, base = 0;
    while (p >= base + i + 1) { base += i + 1; i++; }
    const int l = p - base;
    const int n0 = blockIdx.x * BN;

    const float* xl = x + l * F_DIM;                                   // + b*49152 + k
    const float* Wl = wp.w[i] + (size_t)l * F_DIM * A_DIM + n0;        // + k*768 + n

    uint32_t smb = (uint32_t)__cvta_generic_to_shared(sm);

    float acc[4][4][4];
    #pragma unroll
    for (int q = 0; q < 4; q++)
        #pragma unroll
        for (int r = 0; r < 4; r++)
            #pragma unroll
            for (int s = 0; s < 4; s++) acc[q][r][s] = 0.f;

    auto load_stage = [&](int stage, int k0) {
        uint32_t sb = smb + stage * 32768;
        // A tile: 128 rows (b) x 32 k-floats = 1024 16B-chunks
        #pragma unroll
        for (int j = 0; j < 4; j++) {
            int cid = tid + j * 256;
            int m = cid >> 3, c = cid & 7;
            cp16(sb + (uint32_t)(m * 32 + ((c ^ (m & 7)) << 2)) * 4,
                 xl + (size_t)m * (L_DIM * F_DIM) + k0 + c * 4);
        }
        // B tile: 32 rows (k) x 128 n-floats = 1024 16B-chunks
        uint32_t sbB = sb + 4096 * 4;
        #pragma unroll
        for (int j = 0; j < 4; j++) {
            int cid = tid + j * 256;
            int k = cid >> 5, nc = cid & 31;
            cp16(sbB + (uint32_t)(k * 128 + ((nc ^ (k & 7)) << 2)) * 4,
                 Wl + (size_t)(k0 + k) * A_DIM + nc * 4);
        }
        asm volatile("cp.async.commit_group;");
    };

    load_stage(0, 0);
    asm volatile("cp.async.wait_group 0;");
    __syncthreads();

    const int NCH = F_DIM / BK;  // 128 chunks
    for (int ch = 0; ch < NCH; ch++) {
        const int stage = ch & 1;
        if (ch + 1 < NCH) load_stage(stage ^ 1, (ch + 1) * BK);

        uint32_t asb = smb + stage * 32768;
        const float* Bsf = sm + stage * 8192 + 4096;

        #pragma unroll
        for (int kk = 0; kk < 4; kk++) {       // 4 x k8 steps within BK=32
            // A fragments via ldmatrix.x4 (raw fp32 bits), then cvt to tf32
            uint32_t a[4][4];
            #pragma unroll
            for (int mt = 0; mt < 4; mt++) {
                int m = wm + mt * 16 + (lane & 15);
                int c = kk * 2 + (lane >> 4);
                uint32_t addr = asb + (uint32_t)(m * 32 + ((c ^ (m & 7)) << 2)) * 4;
                asm volatile(
                    "ldmatrix.sync.aligned.m8n8.x4.shared.b16 {%0,%1,%2,%3}, [%4];"
                    : "=r"(a[mt][0]), "=r"(a[mt][1]), "=r"(a[mt][2]), "=r"(a[mt][3])
                    : "r"(addr));
            }
            #pragma unroll
            for (int mt = 0; mt < 4; mt++)
                #pragma unroll
                for (int v = 0; v < 4; v++)
                    a[mt][v] = cvt_tf32(__uint_as_float(a[mt][v]));

            // B fragments: b0 = B[k8 + lane%4][n], b1 = B[k8+4+lane%4][n]
            uint32_t b[4][2];
            #pragma unroll
            for (int nt = 0; nt < 4; nt++) {
                int n  = wn + nt * 8 + (lane >> 2);
                int kl = kk * 8 + (lane & 3);
                int kh = kl + 4;
                float b0 = Bsf[kl * 128 + (((n >> 2) ^ (kl & 7)) << 2) + (n & 3)];
                float b1 = Bsf[kh * 128 + (((n >> 2) ^ (kh & 7)) << 2) + (n & 3)];
                b[nt][0] = cvt_tf32(b0);
                b[nt][1] = cvt_tf32(b1);
            }

            #pragma unroll
            for (int mt = 0; mt < 4; mt++)
                #pragma unroll
                for (int nt = 0; nt < 4; nt++) {
                    asm volatile(
                        "mma.sync.aligned.m16n8k8.row.col.f32.tf32.tf32.f32 "
                        "{%0,%1,%2,%3}, {%4,%5,%6,%7}, {%8,%9}, {%0,%1,%2,%3};"
                        : "+f"(acc[mt][nt][0]), "+f"(acc[mt][nt][1]),
                          "+f"(acc[mt][nt][2]), "+f"(acc[mt][nt][3])
                        : "r"(a[mt][0]), "r"(a[mt][1]), "r"(a[mt][2]), "r"(a[mt][3]),
                          "r"(b[nt][0]), "r"(b[nt][1]));
                }
        }
        asm volatile("cp.async.wait_group 0;");
        __syncthreads();
    }

    // Epilogue: write partial tile to scratch (float2 stores, c-frag layout)
    float* outp = g_scratch + (size_t)p * (B_DIM * A_DIM);
    #pragma unroll
    for (int mt = 0; mt < 4; mt++) {
        int r0 = wm + mt * 16 + (lane >> 2);
        #pragma unroll
        for (int nt = 0; nt < 4; nt++) {
            int cc = n0 + wn + nt * 8 + 2 * (lane & 3);
            float2 v0 = make_float2(acc[mt][nt][0], acc[mt][nt][1]);
            float2 v1 = make_float2(acc[mt][nt][2], acc[mt][nt][3]);
            *reinterpret_cast<float2*>(outp + (size_t)r0 * A_DIM + cc) = v0;
            *reinterpret_cast<float2*>(outp + (size_t)(r0 + 8) * A_DIM + cc) = v1;
        }
    }
}

// Deterministic prefix reduction: Y[b,i,a] = sum_{l<=i} P[tri(i)+l][b,a]
__global__ void reduce_kernel(float* __restrict__ out) {
    int idx = blockIdx.x * blockDim.x + threadIdx.x;
    const int total = B_DIM * L_DIM * A_DIM;
    if (idx >= total) return;
    int a   = idx % A_DIM;
    int rem = idx / A_DIM;
    int i   = rem % L_DIM;
    int b   = rem / L_DIM;
    int base = i * (i + 1) / 2;
    float s = 0.f;
    #pragma unroll 4
    for (int l = 0; l <= i; l++)
        s += g_scratch[(size_t)(base + l) * (B_DIM * A_DIM) + (size_t)b * A_DIM + a];
    out[idx] = s;
}

extern "C" void kernel_launch(void* const* d_in, const int* in_sizes, int n_in,
                              void* d_out, int out_size) {
    const float* x = (const float*)d_in[0];
    WPtrs wp;
    for (int i = 0; i < 12; i++) wp.w[i] = (const float*)d_in[1 + i];

    cudaFuncSetAttribute(reinterpret_cast<const void*>(gemm_pair_kernel),
                         cudaFuncAttributeMaxDynamicSharedMemorySize, 65536);

    dim3 grid(A_DIM / BN, PAIRS);   // 6 n-tiles x 78 (i,l) pairs = 468 CTAs
    gemm_pair_kernel<<<grid, THREADS, 65536>>>(x, wp);

    const int total = B_DIM * L_DIM * A_DIM;
    reduce_kernel<<<(total + 255) / 256, 256>>>((float*)d_out);
}

// round 4
// speedup vs baseline: 1.0333x; 1.0333x over previous
#include <cuda_runtime.h>
#include <cstdint>

#define B_DIM 128
#define L_DIM 12
#define F_DIM 4096
#define A_DIM 768
#define PAIRS 78
#define THREADS 256
#define BK 32
#define NCH (F_DIM / BK)          // 128 chunks
#define STAGE_BYTES 32768         // 16KB A (x) + 16KB Bt (W^T)
#define NSTG 3
#define SMEM_BYTES (NSTG * STAGE_BYTES)   // 98304 -> 2 CTAs/SM

__device__ float g_scratch[(size_t)PAIRS * B_DIM * A_DIM];   // [pair][b][a]
__device__ float g_xtf32[(size_t)B_DIM * L_DIM * F_DIM];     // tf32-rounded x

struct WPtrs { const float* w[12]; };

__device__ __forceinline__ uint32_t smem_u32(const void* p) {
    uint32_t a;
    asm("{ .reg .u64 t; cvta.to.shared.u64 t, %1; cvt.u32.u64 %0, t; }"
        : "=r"(a) : "l"(p));
    return a;
}
__device__ __forceinline__ uint32_t cvt_tf32(float f) {
    uint32_t o; asm volatile("cvt.rna.tf32.f32 %0, %1;" : "=r"(o) : "f"(f)); return o;
}
__device__ __forceinline__ void cp16(uint32_t s, const float* g) {
    asm volatile("cp.async.cg.shared.global [%0], [%1], 16;" :: "r"(s), "l"(g));
}

// ---------------- x pre-round to tf32 (RNA, once) ----------------
__global__ void cvt_x_kernel(const float* __restrict__ x) {
    int idx = blockIdx.x * blockDim.x + threadIdx.x;
    const int n4 = (B_DIM * L_DIM * F_DIM) / 4;
    if (idx >= n4) return;
    float4 v = reinterpret_cast<const float4*>(x)[idx];
    float4 o;
    o.x = __uint_as_float(cvt_tf32(v.x));
    o.y = __uint_as_float(cvt_tf32(v.y));
    o.z = __uint_as_float(cvt_tf32(v.z));
    o.w = __uint_as_float(cvt_tf32(v.w));
    reinterpret_cast<float4*>(g_xtf32)[idx] = o;
}

// ---------------- main GEMM ----------------
// CTA: pair p=(i,l), n-tile n0. Tile: D[128 b][128 a], K=4096 in 32-chunks.
// smem per stage: As[128 b][32 k] (swizzled rows of 128B) then Bt[128 n][32 k] (same).
__global__ __launch_bounds__(THREADS, 2)
void gemm_pair_kernel(WPtrs wp) {
    extern __shared__ char smem[];
    const uint32_t smb = smem_u32(smem);
    const int tid  = threadIdx.x;
    const int lane = tid & 31;
    const int warp = tid >> 5;
    const int wm = (warp >> 2) * 64;   // warp b-row offset (2 warp-rows)
    const int wn = (warp & 3) * 32;    // warp a-col offset (4 warp-cols)

    // pair decode
    int p = blockIdx.y, i = 0, base = 0;
    while (p >= base + i + 1) { base += i + 1; i++; }
    const int l  = p - base;
    const int n0 = blockIdx.x * 128;

    const float* Wl = wp.w[i] + (size_t)l * F_DIM * A_DIM + n0;  // + k*768 + n
    const float* xl = g_xtf32 + (size_t)l * F_DIM;               // + b*49152 + k

    // W staging coords (per thread): one n column, 16 k rows
    const int wn_idx = tid & 127;            // n 0..127
    const int wkh    = (tid >> 7) * 16;      // k-half 0 or 16
    const float* wgp = Wl + wn_idx;          // + k*A_DIM

    float acc[4][4][4];
    #pragma unroll
    for (int q = 0; q < 4; q++)
        #pragma unroll
        for (int r = 0; r < 4; r++)
            #pragma unroll
            for (int s = 0; s < 4; s++) acc[q][r][s] = 0.f;

    // ---- staging helpers ----
    auto stage_x = [&](int s, int k0) {
        uint32_t xb = smb + s * STAGE_BYTES;
        const float* xg = xl + k0;
        #pragma unroll
        for (int j = 0; j < 4; j++) {
            int cid = tid + j * 256;
            int m = cid >> 3, c = cid & 7;
            cp16(xb + (uint32_t)(m * 128 + ((c ^ (m & 7)) << 4)),
                 xg + (size_t)m * (L_DIM * F_DIM) + c * 4);
        }
        asm volatile("cp.async.commit_group;");
    };
    auto ldg_w = [&](int k0, float (&wv)[16]) {
        const float* g = wgp + (size_t)(k0 + wkh) * A_DIM;
        #pragma unroll
        for (int j = 0; j < 16; j++) wv[j] = __ldg(g + (size_t)j * A_DIM);
    };
    auto sts_w = [&](int s, const float (&wv)[16]) {
        uint32_t rowb = smb + s * STAGE_BYTES + 16384 + wn_idx * 128;
        #pragma unroll
        for (int c4 = 0; c4 < 4; c4++) {
            uint32_t q = (uint32_t)((wkh >> 2) + c4);
            uint32_t addr = rowb + ((q ^ (uint32_t)(wn_idx & 7)) << 4);
            uint32_t r0 = cvt_tf32(wv[c4 * 4 + 0]);
            uint32_t r1 = cvt_tf32(wv[c4 * 4 + 1]);
            uint32_t r2 = cvt_tf32(wv[c4 * 4 + 2]);
            uint32_t r3 = cvt_tf32(wv[c4 * 4 + 3]);
            asm volatile("st.shared.v4.b32 [%0], {%1,%2,%3,%4};"
                         :: "r"(addr), "r"(r0), "r"(r1), "r"(r2), "r"(r3) : "memory");
        }
    };

    // ---- compute one chunk from stage s ----
    auto compute = [&](int s) {
        uint32_t abase  = smb + s * STAGE_BYTES;
        uint32_t btbase = abase + 16384;
        #pragma unroll
        for (int kk = 0; kk < 4; kk++) {
            uint32_t a[4][4];
            #pragma unroll
            for (int mt = 0; mt < 4; mt++) {
                int m = wm + mt * 16 + (lane & 15);
                int c = kk * 2 + (lane >> 4);
                uint32_t addr = abase + (uint32_t)(m * 128 + ((c ^ (m & 7)) << 4));
                asm volatile(
                    "ldmatrix.sync.aligned.m8n8.x4.shared.b16 {%0,%1,%2,%3}, [%4];"
                    : "=r"(a[mt][0]), "=r"(a[mt][1]), "=r"(a[mt][2]), "=r"(a[mt][3])
                    : "r"(addr));
            }
            uint32_t b[4][2];
            #pragma unroll
            for (int g2 = 0; g2 < 2; g2++) {
                // x4: m0=(nt=2g2, k-lo), m1=(2g2, k-hi), m2=(2g2+1, lo), m3=(2g2+1, hi)
                int nrow = wn + (2 * g2 + (lane >> 4)) * 8 + (lane & 7);
                int c16  = kk * 2 + ((lane >> 3) & 1);
                uint32_t addr = btbase + (uint32_t)(nrow * 128 + ((c16 ^ (nrow & 7)) << 4));
                asm volatile(
                    "ldmatrix.sync.aligned.m8n8.x4.shared.b16 {%0,%1,%2,%3}, [%4];"
                    : "=r"(b[2*g2][0]), "=r"(b[2*g2][1]),
                      "=r"(b[2*g2+1][0]), "=r"(b[2*g2+1][1])
                    : "r"(addr));
            }
            #pragma unroll
            for (int mt = 0; mt < 4; mt++)
                #pragma unroll
                for (int nt = 0; nt < 4; nt++) {
                    asm volatile(
                        "mma.sync.aligned.m16n8k8.row.col.f32.tf32.tf32.f32 "
                        "{%0,%1,%2,%3}, {%4,%5,%6,%7}, {%8,%9}, {%0,%1,%2,%3};"
                        : "+f"(acc[mt][nt][0]), "+f"(acc[mt][nt][1]),
                          "+f"(acc[mt][nt][2]), "+f"(acc[mt][nt][3])
                        : "r"(a[mt][0]), "r"(a[mt][1]), "r"(a[mt][2]), "r"(a[mt][3]),
                          "r"(b[nt][0]), "r"(b[nt][1]));
                }
        }
    };

    // ---- prologue: stages 0,1 ----
    {
        float wv[16];
        ldg_w(0, wv);  stage_x(0, 0);       sts_w(0, wv);
        ldg_w(BK, wv); stage_x(1, BK);      sts_w(1, wv);
    }

    // ---- main loop ----
    for (int ch = 0; ch < NCH; ch++) {
        if (ch + 1 < NCH) asm volatile("cp.async.wait_group 1;");
        else              asm volatile("cp.async.wait_group 0;");
        __syncthreads();

        const bool pre = (ch + 2 < NCH);
        float wv[16];
        if (pre) {
            ldg_w((ch + 2) * BK, wv);          // LDGs in flight across compute
            stage_x((ch + 2) % NSTG, (ch + 2) * BK);
        }
        compute(ch % NSTG);
        if (pre) sts_w((ch + 2) % NSTG, wv);
    }

    // ---- epilogue: direct float2 stores to scratch [p][b][a] ----
    float* outp = g_scratch + (size_t)p * (B_DIM * A_DIM);
    #pragma unroll
    for (int mt = 0; mt < 4; mt++) {
        int r0 = wm + mt * 16 + (lane >> 2);
        #pragma unroll
        for (int nt = 0; nt < 4; nt++) {
            int cc = n0 + wn + nt * 8 + 2 * (lane & 3);
            float2 v0 = make_float2(acc[mt][nt][0], acc[mt][nt][1]);
            float2 v1 = make_float2(acc[mt][nt][2], acc[mt][nt][3]);
            *reinterpret_cast<float2*>(outp + (size_t)r0 * A_DIM + cc) = v0;
            *reinterpret_cast<float2*>(outp + (size_t)(r0 + 8) * A_DIM + cc) = v1;
        }
    }
}

// ---------------- prefix reduction ----------------
__global__ void reduce_kernel(float* __restrict__ out) {
    int idx = blockIdx.x * blockDim.x + threadIdx.x;
    const int total = B_DIM * L_DIM * A_DIM;
    if (idx >= total) return;
    int a   = idx % A_DIM;
    int rem = idx / A_DIM;
    int i   = rem % L_DIM;
    int b   = rem / L_DIM;
    int base = i * (i + 1) / 2;
    float s = 0.f;
    #pragma unroll 4
    for (int l = 0; l <= i; l++)
        s += g_scratch[(size_t)(base + l) * (B_DIM * A_DIM) + (size_t)b * A_DIM + a];
    out[idx] = s;
}

extern "C" void kernel_launch(void* const* d_in, const int* in_sizes, int n_in,
                              void* d_out, int out_size) {
    const float* x = (const float*)d_in[0];
    WPtrs wp;
    for (int i = 0; i < 12; i++) wp.w[i] = (const float*)d_in[1 + i];

    cudaFuncSetAttribute(reinterpret_cast<const void*>(gemm_pair_kernel),
                         cudaFuncAttributeMaxDynamicSharedMemorySize, SMEM_BYTES);

    const int n4 = (B_DIM * L_DIM * F_DIM) / 4;
    cvt_x_kernel<<<(n4 + 255) / 256, 256>>>(x);

    dim3 grid(A_DIM / 128, PAIRS);   // 6 x 78 = 468 CTAs
    gemm_pair_kernel<<<grid, THREADS, SMEM_BYTES>>>(wp);

    const int total = B_DIM * L_DIM * A_DIM;
    reduce_kernel<<<(total + 255) / 256, 256>>>((float*)d_out);
}

// round 5
// speedup vs baseline: 1.5416x; 1.4919x over previous
#include <cuda_runtime.h>
#include <cuda_fp16.h>
#include <cstdint>

#define B_DIM 128
#define L_DIM 12
#define F_DIM 4096
#define A_DIM 768
#define PAIRS 78
#define THREADS 256
#define BK 64
#define NCH (F_DIM / BK)          // 64 chunks
#define STAGE_BYTES 32768         // 16KB As (x fp16) + 16KB Bt (W^T fp16)
#define NSTG 3
#define SMEM_BYTES (NSTG * STAGE_BYTES)   // 98304 -> 2 CTAs/SM

__device__ float  g_scratch[(size_t)PAIRS * B_DIM * A_DIM];  // [pair][b][a]
__device__ __half g_xf16[(size_t)B_DIM * L_DIM * F_DIM];     // fp16 x

struct WPtrs { const float* w[12]; };

__device__ __forceinline__ uint32_t smem_u32(const void* p) {
    uint32_t a;
    asm("{ .reg .u64 t; cvta.to.shared.u64 t, %1; cvt.u32.u64 %0, t; }"
        : "=r"(a) : "l"(p));
    return a;
}
__device__ __forceinline__ void cp16(uint32_t s, const void* g) {
    asm volatile("cp.async.cg.shared.global [%0], [%1], 16;" :: "r"(s), "l"(g));
}
__device__ __forceinline__ uint32_t pack2(float a, float b) {
    __half2 h = __floats2half2_rn(a, b);
    return *reinterpret_cast<uint32_t*>(&h);
}

// ---------------- x pre-convert to fp16 ----------------
__global__ void cvt_x_kernel(const float* __restrict__ x) {
    int idx = blockIdx.x * blockDim.x + threadIdx.x;
    const int n8 = (B_DIM * L_DIM * F_DIM) / 8;
    if (idx >= n8) return;
    float4 v0 = reinterpret_cast<const float4*>(x)[2 * idx];
    float4 v1 = reinterpret_cast<const float4*>(x)[2 * idx + 1];
    uint4 o;
    o.x = pack2(v0.x, v0.y);
    o.y = pack2(v0.z, v0.w);
    o.z = pack2(v1.x, v1.y);
    o.w = pack2(v1.z, v1.w);
    reinterpret_cast<uint4*>(g_xf16)[idx] = o;
}

// ---------------- main GEMM ----------------
// CTA: pair p=(i,l), n-tile n0. D[128 b][128 a], K=4096 in 64-chunks.
// Stage: As[128 b][64 k fp16] (128B rows, 16B-chunk XOR swizzle), Bt[128 n][64 k fp16].
__global__ __launch_bounds__(THREADS, 2)
void gemm_pair_kernel(WPtrs wp) {
    extern __shared__ char smem[];
    const uint32_t smb = smem_u32(smem);
    const int tid  = threadIdx.x;
    const int lane = tid & 31;
    const int warp = tid >> 5;
    const int wm = (warp >> 2) * 64;   // warp b-row offset
    const int wn = (warp & 3) * 32;    // warp a-col offset

    int p = blockIdx.y, i = 0, base = 0;
    while (p >= base + i + 1) { base += i + 1; i++; }
    const int l  = p - base;
    const int n0 = blockIdx.x * 128;

    const float*  Wl = wp.w[i] + (size_t)l * F_DIM * A_DIM + n0;  // + k*768 + n
    const __half* xl = g_xf16 + (size_t)l * F_DIM;                // + b*49152 + k

    // W staging: thread -> one n column (tid&127), k-base (tid>>7)*32, 2 halves of 16
    const int wn_idx = tid & 127;
    const int wkb    = (tid >> 7) * 32;
    const float* wgp = Wl + wn_idx;

    float acc[4][4][4];
    #pragma unroll
    for (int q = 0; q < 4; q++)
        #pragma unroll
        for (int r = 0; r < 4; r++)
            #pragma unroll
            for (int s = 0; s < 4; s++) acc[q][r][s] = 0.f;

    auto stage_x = [&](int s, int k0) {
        uint32_t xb = smb + s * STAGE_BYTES;
        const __half* xg = xl + k0;
        #pragma unroll
        for (int j = 0; j < 4; j++) {
            int cid = tid + j * 256;
            int m = cid >> 3, c = cid & 7;
            cp16(xb + (uint32_t)(m * 128 + ((c ^ (m & 7)) << 4)),
                 xg + (size_t)m * (L_DIM * F_DIM) + c * 8);
        }
        asm volatile("cp.async.commit_group;");
    };
    auto ldg_w = [&](int k0, int h, float (&wv)[16]) {
        const float* g = wgp + (size_t)(k0 + wkb + h * 16) * A_DIM;
        #pragma unroll
        for (int j = 0; j < 16; j++) wv[j] = __ldg(g + (size_t)j * A_DIM);
    };
    auto sts_w = [&](int s, int h, const float (&wv)[16]) {
        uint32_t rowb = smb + s * STAGE_BYTES + 16384 + wn_idx * 128;
        #pragma unroll
        for (int c2 = 0; c2 < 2; c2++) {
            uint32_t q = (uint32_t)((wkb >> 3) + h * 2 + c2);
            uint32_t addr = rowb + ((q ^ (uint32_t)(wn_idx & 7)) << 4);
            uint32_t r0 = pack2(wv[c2 * 8 + 0], wv[c2 * 8 + 1]);
            uint32_t r1 = pack2(wv[c2 * 8 + 2], wv[c2 * 8 + 3]);
            uint32_t r2 = pack2(wv[c2 * 8 + 4], wv[c2 * 8 + 5]);
            uint32_t r3 = pack2(wv[c2 * 8 + 6], wv[c2 * 8 + 7]);
            asm volatile("st.shared.v4.b32 [%0], {%1,%2,%3,%4};"
                         :: "r"(addr), "r"(r0), "r"(r1), "r"(r2), "r"(r3) : "memory");
        }
    };

    // compute one k16 block kk (0..3) from stage s
    auto compute_kk = [&](int s, int kk) {
        uint32_t abase  = smb + s * STAGE_BYTES;
        uint32_t btbase = abase + 16384;
        uint32_t a[4][4];
        #pragma unroll
        for (int mt = 0; mt < 4; mt++) {
            int m = wm + mt * 16 + (lane & 15);
            int c = kk * 2 + (lane >> 4);
            uint32_t addr = abase + (uint32_t)(m * 128 + ((c ^ (m & 7)) << 4));
            asm volatile(
                "ldmatrix.sync.aligned.m8n8.x4.shared.b16 {%0,%1,%2,%3}, [%4];"
                : "=r"(a[mt][0]), "=r"(a[mt][1]), "=r"(a[mt][2]), "=r"(a[mt][3])
                : "r"(addr));
        }
        uint32_t b[4][2];
        #pragma unroll
        for (int g2 = 0; g2 < 2; g2++) {
            int nrow = wn + (2 * g2 + (lane >> 4)) * 8 + (lane & 7);
            int c16  = kk * 2 + ((lane >> 3) & 1);
            uint32_t addr = btbase + (uint32_t)(nrow * 128 + ((c16 ^ (nrow & 7)) << 4));
            asm volatile(
                "ldmatrix.sync.aligned.m8n8.x4.shared.b16 {%0,%1,%2,%3}, [%4];"
                : "=r"(b[2*g2][0]), "=r"(b[2*g2][1]),
                  "=r"(b[2*g2+1][0]), "=r"(b[2*g2+1][1])
                : "r"(addr));
        }
        #pragma unroll
        for (int mt = 0; mt < 4; mt++)
            #pragma unroll
            for (int nt = 0; nt < 4; nt++) {
                asm volatile(
                    "mma.sync.aligned.m16n8k16.row.col.f32.f16.f16.f32 "
                    "{%0,%1,%2,%3}, {%4,%5,%6,%7}, {%8,%9}, {%0,%1,%2,%3};"
                    : "+f"(acc[mt][nt][0]), "+f"(acc[mt][nt][1]),
                      "+f"(acc[mt][nt][2]), "+f"(acc[mt][nt][3])
                    : "r"(a[mt][0]), "r"(a[mt][1]), "r"(a[mt][2]), "r"(a[mt][3]),
                      "r"(b[nt][0]), "r"(b[nt][1]));
            }
    };

    // ---- prologue: stages 0,1 ----
    {
        float wv[16];
        stage_x(0, 0);
        ldg_w(0, 0, wv);  sts_w(0, 0, wv);
        ldg_w(0, 1, wv);  sts_w(0, 1, wv);
        stage_x(1, BK);
        ldg_w(BK, 0, wv); sts_w(1, 0, wv);
        ldg_w(BK, 1, wv); sts_w(1, 1, wv);
    }

    // ---- main loop ----
    for (int ch = 0; ch < NCH; ch++) {
        if (ch + 1 < NCH) asm volatile("cp.async.wait_group 1;");
        else              asm volatile("cp.async.wait_group 0;");
        __syncthreads();

        const int s = ch % NSTG;
        if (ch + 2 < NCH) {
            const int sn = (ch + 2) % NSTG, kn = (ch + 2) * BK;
            float wv[16];
            ldg_w(kn, 0, wv);            // LDGs in flight over compute
            stage_x(sn, kn);
            compute_kk(s, 0);
            compute_kk(s, 1);
            sts_w(sn, 0, wv);
            ldg_w(kn, 1, wv);
            compute_kk(s, 2);
            compute_kk(s, 3);
            sts_w(sn, 1, wv);
        } else {
            compute_kk(s, 0);
            compute_kk(s, 1);
            compute_kk(s, 2);
            compute_kk(s, 3);
        }
    }

    // ---- epilogue: float2 stores to scratch [p][b][a] ----
    float* outp = g_scratch + (size_t)p * (B_DIM * A_DIM);
    #pragma unroll
    for (int mt = 0; mt < 4; mt++) {
        int r0 = wm + mt * 16 + (lane >> 2);
        #pragma unroll
        for (int nt = 0; nt < 4; nt++) {
            int cc = n0 + wn + nt * 8 + 2 * (lane & 3);
            float2 v0 = make_float2(acc[mt][nt][0], acc[mt][nt][1]);
            float2 v1 = make_float2(acc[mt][nt][2], acc[mt][nt][3]);
            *reinterpret_cast<float2*>(outp + (size_t)r0 * A_DIM + cc) = v0;
            *reinterpret_cast<float2*>(outp + (size_t)(r0 + 8) * A_DIM + cc) = v1;
        }
    }
}

// ---------------- prefix reduction ----------------
__global__ void reduce_kernel(float* __restrict__ out) {
    int idx = blockIdx.x * blockDim.x + threadIdx.x;
    const int total = B_DIM * L_DIM * A_DIM;
    if (idx >= total) return;
    int a   = idx % A_DIM;
    int rem = idx / A_DIM;
    int i   = rem % L_DIM;
    int b   = rem / L_DIM;
    int base = i * (i + 1) / 2;
    float s = 0.f;
    #pragma unroll 4
    for (int l = 0; l <= i; l++)
        s += g_scratch[(size_t)(base + l) * (B_DIM * A_DIM) + (size_t)b * A_DIM + a];
    out[idx] = s;
}

extern "C" void kernel_launch(void* const* d_in, const int* in_sizes, int n_in,
                              void* d_out, int out_size) {
    const float* x = (const float*)d_in[0];
    WPtrs wp;
    for (int i = 0; i < 12; i++) wp.w[i] = (const float*)d_in[1 + i];

    cudaFuncSetAttribute(reinterpret_cast<const void*>(gemm_pair_kernel),
                         cudaFuncAttributeMaxDynamicSharedMemorySize, SMEM_BYTES);

    const int n8 = (B_DIM * L_DIM * F_DIM) / 8;
    cvt_x_kernel<<<(n8 + 255) / 256, 256>>>(x);

    dim3 grid(A_DIM / 128, PAIRS);   // 6 x 78 = 468 CTAs
    gemm_pair_kernel<<<grid, THREADS, SMEM_BYTES>>>(wp);

    const int total = B_DIM * L_DIM * A_DIM;
    reduce_kernel<<<(total + 255) / 256, 256>>>((float*)d_out);
}

// round 6
// speedup vs baseline: 1.5792x; 1.0244x over previous
#include <cuda_runtime.h>
#include <cuda_fp16.h>
#include <cstdint>

#define B_DIM 128
#define L_DIM 12
#define F_DIM 4096
#define A_DIM 768
#define PAIRS 78
#define NTILES (PAIRS * 6)        // 468
#define NFULL 296                 // full-K units (fill 2x148 residency exactly)
#define NSPLIT (NTILES - NFULL)   // 172 tiles split into 4 K-quarters
#define NUNITS (NFULL + NSPLIT * 4)   // 984
#define THREADS 256
#define BK 64
#define STAGE_BYTES 32768
#define NSTG 3
#define SMEM_BYTES (NSTG * STAGE_BYTES)   // 98304 -> 2 CTAs/SM

__device__ float  g_s1[(size_t)NFULL * 16384];        // full tiles  [t][b][aloc]
__device__ float  g_s2[(size_t)NSPLIT * 4 * 16384];   // quarters    [u][b][aloc]
__device__ __half g_xf16[(size_t)B_DIM * L_DIM * F_DIM];

struct WPtrs { const float* w[12]; };

__device__ __forceinline__ uint32_t smem_u32(const void* p) {
    uint32_t a;
    asm("{ .reg .u64 t; cvta.to.shared.u64 t, %1; cvt.u32.u64 %0, t; }"
        : "=r"(a) : "l"(p));
    return a;
}
__device__ __forceinline__ void cp16(uint32_t s, const void* g) {
    asm volatile("cp.async.cg.shared.global [%0], [%1], 16;" :: "r"(s), "l"(g));
}
__device__ __forceinline__ uint32_t pack2(float a, float b) {
    __half2 h = __floats2half2_rn(a, b);
    return *reinterpret_cast<uint32_t*>(&h);
}

// ---------------- x pre-convert to fp16 ----------------
__global__ void cvt_x_kernel(const float* __restrict__ x) {
    int idx = blockIdx.x * blockDim.x + threadIdx.x;
    const int n8 = (B_DIM * L_DIM * F_DIM) / 8;
    if (idx >= n8) return;
    float4 v0 = reinterpret_cast<const float4*>(x)[2 * idx];
    float4 v1 = reinterpret_cast<const float4*>(x)[2 * idx + 1];
    uint4 o;
    o.x = pack2(v0.x, v0.y);
    o.y = pack2(v0.z, v0.w);
    o.z = pack2(v1.x, v1.y);
    o.w = pack2(v1.z, v1.w);
    reinterpret_cast<uint4*>(g_xf16)[idx] = o;
}

// ---------------- main GEMM (mixed-size units) ----------------
__global__ __launch_bounds__(THREADS, 2)
void gemm_pair_kernel(WPtrs wp) {
    extern __shared__ char smem[];
    const uint32_t smb = smem_u32(smem);
    const int tid  = threadIdx.x;
    const int lane = tid & 31;
    const int warp = tid >> 5;
    const int wm = (warp >> 2) * 64;
    const int wn = (warp & 3) * 32;

    // ---- unit decode ----
    int bid = blockIdx.x;
    int tile, k0c, nch;
    float* outp;
    if (bid < NFULL) {
        tile = bid; k0c = 0; nch = 64;
        outp = g_s1 + (size_t)bid * 16384;
    } else {
        int u = bid - NFULL;
        tile = NFULL + (u >> 2);
        k0c  = (u & 3) * 16;
        nch  = 16;
        outp = g_s2 + (size_t)u * 16384;
    }
    const int p_  = tile / 6;
    const int ntc = tile % 6;
    const int n0  = ntc * 128;

    int p = p_, i = 0, base = 0;
    while (p >= base + i + 1) { base += i + 1; i++; }
    const int l = p - base;

    const float*  Wl = wp.w[i] + (size_t)l * F_DIM * A_DIM + n0;
    const __half* xl = g_xf16 + (size_t)l * F_DIM;

    const int wn_idx = tid & 127;
    const int wkb    = (tid >> 7) * 32;
    const float* wgp = Wl + wn_idx;

    float acc[4][4][4];
    #pragma unroll
    for (int q = 0; q < 4; q++)
        #pragma unroll
        for (int r = 0; r < 4; r++)
            #pragma unroll
            for (int s = 0; s < 4; s++) acc[q][r][s] = 0.f;

    auto stage_x = [&](int s, int kel) {
        uint32_t xb = smb + s * STAGE_BYTES;
        const __half* xg = xl + kel;
        #pragma unroll
        for (int j = 0; j < 4; j++) {
            int cid = tid + j * 256;
            int m = cid >> 3, c = cid & 7;
            cp16(xb + (uint32_t)(m * 128 + ((c ^ (m & 7)) << 4)),
                 xg + (size_t)m * (L_DIM * F_DIM) + c * 8);
        }
        asm volatile("cp.async.commit_group;");
    };
    auto ldg_w = [&](int kel, int h, float (&wv)[16]) {
        const float* g = wgp + (size_t)(kel + wkb + h * 16) * A_DIM;
        #pragma unroll
        for (int j = 0; j < 16; j++) wv[j] = __ldg(g + (size_t)j * A_DIM);
    };
    auto sts_w = [&](int s, int h, const float (&wv)[16]) {
        uint32_t rowb = smb + s * STAGE_BYTES + 16384 + wn_idx * 128;
        #pragma unroll
        for (int c2 = 0; c2 < 2; c2++) {
            uint32_t q = (uint32_t)((wkb >> 3) + h * 2 + c2);
            uint32_t addr = rowb + ((q ^ (uint32_t)(wn_idx & 7)) << 4);
            uint32_t r0 = pack2(wv[c2 * 8 + 0], wv[c2 * 8 + 1]);
            uint32_t r1 = pack2(wv[c2 * 8 + 2], wv[c2 * 8 + 3]);
            uint32_t r2 = pack2(wv[c2 * 8 + 4], wv[c2 * 8 + 5]);
            uint32_t r3 = pack2(wv[c2 * 8 + 6], wv[c2 * 8 + 7]);
            asm volatile("st.shared.v4.b32 [%0], {%1,%2,%3,%4};"
                         :: "r"(addr), "r"(r0), "r"(r1), "r"(r2), "r"(r3) : "memory");
        }
    };

    auto compute_kk = [&](int s, int kk) {
        uint32_t abase  = smb + s * STAGE_BYTES;
        uint32_t btbase = abase + 16384;
        uint32_t a[4][4];
        #pragma unroll
        for (int mt = 0; mt < 4; mt++) {
            int m = wm + mt * 16 + (lane & 15);
            int c = kk * 2 + (lane >> 4);
            uint32_t addr = abase + (uint32_t)(m * 128 + ((c ^ (m & 7)) << 4));
            asm volatile(
                "ldmatrix.sync.aligned.m8n8.x4.shared.b16 {%0,%1,%2,%3}, [%4];"
                : "=r"(a[mt][0]), "=r"(a[mt][1]), "=r"(a[mt][2]), "=r"(a[mt][3])
                : "r"(addr));
        }
        uint32_t b[4][2];
        #pragma unroll
        for (int g2 = 0; g2 < 2; g2++) {
            int nrow = wn + (2 * g2 + (lane >> 4)) * 8 + (lane & 7);
            int c16  = kk * 2 + ((lane >> 3) & 1);
            uint32_t addr = btbase + (uint32_t)(nrow * 128 + ((c16 ^ (nrow & 7)) << 4));
            asm volatile(
                "ldmatrix.sync.aligned.m8n8.x4.shared.b16 {%0,%1,%2,%3}, [%4];"
                : "=r"(b[2*g2][0]), "=r"(b[2*g2][1]),
                  "=r"(b[2*g2+1][0]), "=r"(b[2*g2+1][1])
                : "r"(addr));
        }
        #pragma unroll
        for (int mt = 0; mt < 4; mt++)
            #pragma unroll
            for (int nt = 0; nt < 4; nt++) {
                asm volatile(
                    "mma.sync.aligned.m16n8k16.row.col.f32.f16.f16.f32 "
                    "{%0,%1,%2,%3}, {%4,%5,%6,%7}, {%8,%9}, {%0,%1,%2,%3};"
                    : "+f"(acc[mt][nt][0]), "+f"(acc[mt][nt][1]),
                      "+f"(acc[mt][nt][2]), "+f"(acc[mt][nt][3])
                    : "r"(a[mt][0]), "r"(a[mt][1]), "r"(a[mt][2]), "r"(a[mt][3]),
                      "r"(b[nt][0]), "r"(b[nt][1]));
            }
    };

    const int k0e = k0c * BK;
    // ---- prologue: stages 0,1 ----
    {
        float wv[16];
        stage_x(0, k0e);
        ldg_w(k0e, 0, wv);      sts_w(0, 0, wv);
        ldg_w(k0e, 1, wv);      sts_w(0, 1, wv);
        stage_x(1, k0e + BK);
        ldg_w(k0e + BK, 0, wv); sts_w(1, 0, wv);
        ldg_w(k0e + BK, 1, wv); sts_w(1, 1, wv);
    }

    // ---- main loop ----
    for (int ch = 0; ch < nch; ch++) {
        if (ch + 1 < nch) asm volatile("cp.async.wait_group 1;");
        else              asm volatile("cp.async.wait_group 0;");
        __syncthreads();

        const int s = ch % NSTG;
        if (ch + 2 < nch) {
            const int sn = (ch + 2) % NSTG;
            const int kn = k0e + (ch + 2) * BK;
            float wv[16];
            ldg_w(kn, 0, wv);
            stage_x(sn, kn);
            compute_kk(s, 0);
            compute_kk(s, 1);
            sts_w(sn, 0, wv);
            ldg_w(kn, 1, wv);
            compute_kk(s, 2);
            compute_kk(s, 3);
            sts_w(sn, 1, wv);
        } else {
            compute_kk(s, 0);
            compute_kk(s, 1);
            compute_kk(s, 2);
            compute_kk(s, 3);
        }
    }

    // ---- epilogue: slot layout [b][aloc], stride 128 ----
    #pragma unroll
    for (int mt = 0; mt < 4; mt++) {
        int r0 = wm + mt * 16 + (lane >> 2);
        #pragma unroll
        for (int nt = 0; nt < 4; nt++) {
            int cc = wn + nt * 8 + 2 * (lane & 3);
            float2 v0 = make_float2(acc[mt][nt][0], acc[mt][nt][1]);
            float2 v1 = make_float2(acc[mt][nt][2], acc[mt][nt][3]);
            *reinterpret_cast<float2*>(outp + (size_t)r0 * 128 + cc) = v0;
            *reinterpret_cast<float2*>(outp + (size_t)(r0 + 8) * 128 + cc) = v1;
        }
    }
}

// ---------------- reduction: K-quarters + prefix-l, float4 ----------------
__global__ void reduce_kernel(float* __restrict__ out) {
    int idx = blockIdx.x * blockDim.x + threadIdx.x;
    const int total4 = (B_DIM * L_DIM * A_DIM) / 4;
    if (idx >= total4) return;
    int a    = idx * 4;
    int aloc = a & 127;
    int ntc  = (a >> 7) % 6;
    int rem  = idx / (A_DIM / 4);
    int i    = rem % L_DIM;
    int b    = rem / L_DIM;
    int base = i * (i + 1) / 2;

    float4 s = make_float4(0.f, 0.f, 0.f, 0.f);
    for (int l = 0; l <= i; l++) {
        int t = (base + l) * 6 + ntc;
        if (t < NFULL) {
            float4 v = *reinterpret_cast<const float4*>(
                g_s1 + (size_t)t * 16384 + (size_t)b * 128 + aloc);
            s.x += v.x; s.y += v.y; s.z += v.z; s.w += v.w;
        } else {
            const float* pbase = g_s2 + (size_t)(t - NFULL) * 4 * 16384
                               + (size_t)b * 128 + aloc;
            #pragma unroll
            for (int q = 0; q < 4; q++) {
                float4 v = *reinterpret_cast<const float4*>(pbase + (size_t)q * 16384);
                s.x += v.x; s.y += v.y; s.z += v.z; s.w += v.w;
            }
        }
    }
    reinterpret_cast<float4*>(out)[idx] = s;
}

extern "C" void kernel_launch(void* const* d_in, const int* in_sizes, int n_in,
                              void* d_out, int out_size) {
    const float* x = (const float*)d_in[0];
    WPtrs wp;
    for (int i = 0; i < 12; i++) wp.w[i] = (const float*)d_in[1 + i];

    cudaFuncSetAttribute(reinterpret_cast<const void*>(gemm_pair_kernel),
                         cudaFuncAttributeMaxDynamicSharedMemorySize, SMEM_BYTES);

    const int n8 = (B_DIM * L_DIM * F_DIM) / 8;
    cvt_x_kernel<<<(n8 + 255) / 256, 256>>>(x);

    gemm_pair_kernel<<<NUNITS, THREADS, SMEM_BYTES>>>(wp);

    const int total4 = (B_DIM * L_DIM * A_DIM) / 4;
    reduce_kernel<<<(total4 + 255) / 256, 256>>>((float*)d_out);
}